// round 14
// baseline (speedup 1.0000x reference)
#include <cuda_runtime.h>
#include <cstddef>

#define C_DIM 64
#define K_DIM 64
#define P_DIM (256 * 256)        // H*W = 65536
#define REGION_BLOCKS K_DIM      // one block per region, writes its means row
#define SEG 8192                 // pixel segment (smem list worst-case bound)
#define NSEG (P_DIM / SEG)       // 8
#define CHUNKS_PER_REP 2048      // 8 KB chunks (measured optimum)
#define COPY_BLOCKS (K_DIM * CHUNKS_PER_REP)        // 131072
#define N4_PER_REP (C_DIM * P_DIM / 4)              // 1,048,576 float4 per replica
#define F4_PER_CHUNK (N4_PER_REP / CHUNKS_PER_REP)  // 512 float4 = 8KB

// ---------------------------------------------------------------------------
// Single fused kernel:
//   blocks [0, 64)   : region block k — scan oh[k,:], compact hit pixels,
//                      gather x, reduce, write out_means[k*64..] directly.
//                      Fully self-contained: no global atomics, no 2nd kernel.
//   blocks [64, ...) : 1 GiB broadcast copy, 8 KB chunks (proven optimum).
// ---------------------------------------------------------------------------
__global__ __launch_bounds__(256) void fused_kernel(
    const float* __restrict__ x, const float* __restrict__ oh,
    float4* __restrict__ out4, float* __restrict__ out_means)
{
    int bid = blockIdx.x;
    int tid = threadIdx.x;

    if (bid < REGION_BLOCKS) {
        // ---- region path: block owns region k = bid ----
        __shared__ int   s_list[SEG];     // hit pixel indices (32 KB)
        __shared__ int   s_n;             // hits in current segment
        __shared__ int   s_total;         // total hits (region pixel count)
        __shared__ float s_sum[C_DIM];

        const float* ohk = oh + (size_t)bid * P_DIM;
        int lane = tid & 31;
        int wrp  = tid >> 5;

        float acc0 = 0.0f;   // channel = lane
        float acc1 = 0.0f;   // channel = lane + 32

        if (tid == 0) s_total = 0;

        for (int s = 0; s < NSEG; s++) {
            if (tid == 0) s_n = 0;
            __syncthreads();

            // Scan & compact this 8192-pixel segment (coalesced loads).
            int base = s * SEG;
            #pragma unroll
            for (int j = 0; j < SEG / 256; j++) {
                int p = base + j * 256 + tid;
                if (__ldg(&ohk[p]) != 0.0f) {
                    int pos = atomicAdd(&s_n, 1);
                    s_list[pos] = p;
                }
            }
            __syncthreads();

            // Gather: warps stride over hit pixels; lanes cover channels.
            int n = s_n;
            for (int idx = wrp; idx < n; idx += 8) {
                int p = s_list[idx];
                acc0 += __ldg(&x[(size_t)lane * P_DIM + p]);
                acc1 += __ldg(&x[(size_t)(lane + 32) * P_DIM + p]);
            }
            if (tid == 0) s_total += n;
            __syncthreads();
        }

        // Cross-warp reduce (8 warps x 64 channels) via smem atomics.
        if (tid < C_DIM) s_sum[tid] = 0.0f;
        __syncthreads();
        atomicAdd(&s_sum[lane], acc0);
        atomicAdd(&s_sum[lane + 32], acc1);
        __syncthreads();

        if (tid < C_DIM) {
            float cnt = (float)s_total;
            float denom = cnt + (cnt == 0.0f ? 1.0f : 0.0f);
            out_means[bid * C_DIM + tid] = s_sum[tid] / denom;
        }
    } else {
        // ---- broadcast path: one 8 KB chunk of one replica ----
        int b  = bid - REGION_BLOCKS;
        int k  = b >> 11;                    // replica index (2048 chunks/rep)
        int cb = b & (CHUNKS_PER_REP - 1);

        const float4* src = (const float4*)x + (size_t)cb * F4_PER_CHUNK;
        float4* dst = out4 + (size_t)k * N4_PER_REP + (size_t)cb * F4_PER_CHUNK;

        float4 v0 = __ldg(src + tid);
        float4 v1 = __ldg(src + 256 + tid);
        __stcs(dst + tid,       v0);
        __stcs(dst + 256 + tid, v1);
    }
}

// ---------------------------------------------------------------------------
extern "C" void kernel_launch(void* const* d_in, const int* in_sizes, int n_in,
                              void* d_out, int out_size)
{
    const float* x  = (const float*)d_in[0];   // [1, 64, 256, 256]
    const float* oh = (const float*)d_in[1];   // [1, 64, 256, 256] one-hot
    float* out = (float*)d_out;

    // Output layout: input_r (K*C*H*W floats) then regional_means (K*C).
    float* out_means = out + (size_t)out_size - (size_t)(K_DIM * C_DIM);

    fused_kernel<<<REGION_BLOCKS + COPY_BLOCKS, 256>>>(
        x, oh, (float4*)out, out_means);
}

// round 15
// speedup vs baseline: 1.1702x; 1.1702x over previous
#include <cuda_runtime.h>
#include <cstddef>

#define C_DIM 64
#define K_DIM 64
#define P_DIM (256 * 256)        // H*W = 65536
#define RED_BLOCKS 256           // reduction blocks (256 pixels each)
#define CHUNKS_PER_REP 2048      // 8 KB chunks — measured optimum
#define COPY_BLOCKS (K_DIM * CHUNKS_PER_REP)        // 131072
#define N4_PER_REP (C_DIM * P_DIM / 4)              // 1,048,576 float4 per replica
#define F4_PER_CHUNK (N4_PER_REP / CHUNKS_PER_REP)  // 512 float4 = 8KB

// Global accumulators. Zero-initialized at load; the means kernel re-zeroes
// them at the end of every launch, so every graph replay starts from zero.
__device__ float g_sums[K_DIM * C_DIM];   // 16 KB
__device__ float g_counts[K_DIM];

// ---------------------------------------------------------------------------
// Fused kernel (champion structure): blocks [0,256) reduce, rest stream the
// 1 GiB broadcast at the DRAM write ceiling (~6.6 TB/s, 82% of spec).
// Reduction flushes via spread global atomics, fully hidden under the copy.
// ---------------------------------------------------------------------------
__global__ __launch_bounds__(256) void fused_kernel(
    const float* __restrict__ x, const float* __restrict__ oh,
    float4* __restrict__ out4)
{
    int bid = blockIdx.x;
    int tid = threadIdx.x;

    if (bid < RED_BLOCKS) {
        // ---- reduction path: 256 pixels per block ----
        __shared__ float ssum[K_DIM][C_DIM + 1];  // padded rows vs bank conflicts
        __shared__ float scnt[K_DIM];

        for (int i = tid; i < K_DIM * (C_DIM + 1); i += 256)
            (&ssum[0][0])[i] = 0.0f;
        if (tid < K_DIM) scnt[tid] = 0.0f;
        __syncthreads();

        int p = bid * 256 + tid;

        // Recover the one-hot label (coalesced scan over K).
        int label = 0;
        #pragma unroll 8
        for (int k = 0; k < K_DIM; k++) {
            if (__ldg(&oh[(size_t)k * P_DIM + p]) != 0.0f) label = k;
        }
        atomicAdd(&scnt[label], 1.0f);

        #pragma unroll 8
        for (int c = 0; c < C_DIM; c++) {
            atomicAdd(&ssum[label][c], __ldg(&x[(size_t)c * P_DIM + p]));
        }
        __syncthreads();

        // Flush block partials via global atomics (4096 spread addresses,
        // hidden under the DRAM-bound copy).
        for (int i = tid; i < K_DIM * C_DIM; i += 256) {
            float v = ssum[i >> 6][i & 63];
            if (v != 0.0f) atomicAdd(&g_sums[i], v);
        }
        if (tid < K_DIM) {
            float v = scnt[tid];
            if (v != 0.0f) atomicAdd(&g_counts[tid], v);
        }
    } else {
        // ---- broadcast path: one 8 KB chunk of one replica ----
        int b  = bid - RED_BLOCKS;
        int k  = b >> 11;                    // replica index (2048 chunks/rep)
        int cb = b & (CHUNKS_PER_REP - 1);

        const float4* src = (const float4*)x + (size_t)cb * F4_PER_CHUNK;
        float4* dst = out4 + (size_t)k * N4_PER_REP + (size_t)cb * F4_PER_CHUNK;

        float4 v0 = __ldg(src + tid);
        float4 v1 = __ldg(src + 256 + tid);
        __stcs(dst + tid,       v0);
        __stcs(dst + 256 + tid, v1);
    }
}

// ---------------------------------------------------------------------------
// Means: one thread per (k,c); 16 KB of reads, one divide. Self-resets the
// accumulators for the next graph replay (block-exclusive k ranges). Reset
// stores issue before the divide (independent -> shorter dependent tail).
// ---------------------------------------------------------------------------
__global__ __launch_bounds__(256) void means_kernel(float* __restrict__ out_means)
{
    int i = blockIdx.x * 256 + threadIdx.x;   // 0..4095
    int k = i >> 6;

    float s   = g_sums[i];
    float cnt = g_counts[k];

    __syncthreads();   // all reads of this block's g_counts range done

    g_sums[i] = 0.0f;
    if ((i & 63) == 0) g_counts[k] = 0.0f;   // k exclusive to this block

    float denom = cnt + (cnt == 0.0f ? 1.0f : 0.0f);
    out_means[i] = s / denom;
}

// ---------------------------------------------------------------------------
extern "C" void kernel_launch(void* const* d_in, const int* in_sizes, int n_in,
                              void* d_out, int out_size)
{
    const float* x  = (const float*)d_in[0];   // [1, 64, 256, 256]
    const float* oh = (const float*)d_in[1];   // [1, 64, 256, 256] one-hot
    float* out = (float*)d_out;

    // Output layout: input_r (K*C*H*W floats) then regional_means (K*C).
    float* out_means = out + (size_t)out_size - (size_t)(K_DIM * C_DIM);

    fused_kernel<<<RED_BLOCKS + COPY_BLOCKS, 256>>>(x, oh, (float4*)out);
    means_kernel<<<(K_DIM * C_DIM) / 256, 256>>>(out_means);
}